// round 3
// baseline (speedup 1.0000x reference)
#include <cuda_runtime.h>

#define NB 8
#define NM 512
#define ND 64
#define TILE_I 16
#define CHUNK_J 128
#define THREADS 256
#define KSTRIDE 68          // padded row stride (floats) for k/v tiles
#define SSTRIDE 516         // padded row stride (floats) for the score matrix

// shared layout (floats)
#define OFF_SCORES 0
#define OFF_VI     (TILE_I * SSTRIDE)                    // 8256
#define OFF_KJ     (OFF_VI + TILE_I * KSTRIDE)           // 9344
#define OFF_INV    (OFF_KJ + CHUNK_J * KSTRIDE)          // 18048
#define SMEM_FLOATS (OFF_INV + TILE_I)                   // 18064
#define SMEM_BYTES  (SMEM_FLOATS * 4)                    // 72256

__global__ __launch_bounds__(THREADS, 1)
void laplace_attn_kernel(const float* __restrict__ k,
                         const float* __restrict__ v,
                         float* __restrict__ out) {
    extern __shared__ float smem[];
    float* s_scores = smem + OFF_SCORES;   // [TILE_I][SSTRIDE]
    float* s_vi     = smem + OFF_VI;       // [TILE_I][KSTRIDE]
    float* s_kj     = smem + OFF_KJ;       // [CHUNK_J][KSTRIDE]
    float* s_inv    = smem + OFF_INV;      // [TILE_I]

    const int tid = threadIdx.x;
    const int b  = blockIdx.x / (NM / TILE_I);
    const int i0 = (blockIdx.x % (NM / TILE_I)) * TILE_I;

    // ---- stage v rows for this i-tile ----
    {
        const float4* src = (const float4*)(v + (size_t)(b * NM + i0) * ND);
        for (int e = tid; e < TILE_I * ND / 4; e += THREADS) {
            int idx = e * 4;
            int row = idx / ND, col = idx % ND;
            *(float4*)&s_vi[row * KSTRIDE + col] = src[e];
        }
    }

    // ---- Pass A: scores[i][j] = 0.5 * sum_d |k[b,j,d] - v[b,i,d]| ----
    const int tx = tid & 31;           // j direction (32 lanes)
    const int ty = tid >> 5;           // 8 groups
    const int ia = ty * 2;             // two local i rows

    for (int jc = 0; jc < NM; jc += CHUNK_J) {
        __syncthreads();               // prior consumers of s_kj done (also covers s_vi fill)
        {
            const float4* src = (const float4*)(k + (size_t)(b * NM + jc) * ND);
            for (int e = tid; e < CHUNK_J * ND / 4; e += THREADS) {
                int idx = e * 4;
                int row = idx / ND, col = idx % ND;
                *(float4*)&s_kj[row * KSTRIDE + col] = src[e];
            }
        }
        __syncthreads();

        float acc0[4] = {0.f, 0.f, 0.f, 0.f};
        float acc1[4] = {0.f, 0.f, 0.f, 0.f};

        #pragma unroll
        for (int d = 0; d < ND; d += 4) {
            float4 a0 = *(const float4*)&s_vi[ia * KSTRIDE + d];
            float4 a1 = *(const float4*)&s_vi[(ia + 1) * KSTRIDE + d];
            #pragma unroll
            for (int jj = 0; jj < 4; ++jj) {
                float4 kb = *(const float4*)&s_kj[(tx + 32 * jj) * KSTRIDE + d];
                acc0[jj] += fabsf(a0.x - kb.x) + fabsf(a0.y - kb.y)
                          + fabsf(a0.z - kb.z) + fabsf(a0.w - kb.w);
                acc1[jj] += fabsf(a1.x - kb.x) + fabsf(a1.y - kb.y)
                          + fabsf(a1.z - kb.z) + fabsf(a1.w - kb.w);
            }
        }
        #pragma unroll
        for (int jj = 0; jj < 4; ++jj) {
            int j = jc + tx + 32 * jj;
            s_scores[ia * SSTRIDE + j]       = 0.5f * acc0[jj];
            s_scores[(ia + 1) * SSTRIDE + j] = 0.5f * acc1[jj];
        }
    }
    __syncthreads();

    // ---- softmax over j per row (normalization deferred via s_inv) ----
    {
        const int warp = tid >> 5, lane = tid & 31;
        for (int r = warp; r < TILE_I; r += (THREADS / 32)) {
            float mx = -1e30f;
            for (int j = lane; j < NM; j += 32)
                mx = fmaxf(mx, s_scores[r * SSTRIDE + j]);
            #pragma unroll
            for (int off = 16; off > 0; off >>= 1)
                mx = fmaxf(mx, __shfl_xor_sync(0xffffffffu, mx, off));

            float sum = 0.f;
            for (int j = lane; j < NM; j += 32) {
                float e = __expf(s_scores[r * SSTRIDE + j] - mx);
                s_scores[r * SSTRIDE + j] = e;
                sum += e;
            }
            #pragma unroll
            for (int off = 16; off > 0; off >>= 1)
                sum += __shfl_xor_sync(0xffffffffu, sum, off);

            if (lane == 0) s_inv[r] = 1.f / sum;
        }
    }

    // ---- Pass B: rep[i][d] = inv[i] * sum_j e[i][j] * v[b,j,d] ----
    const int dx = (tid & 15) * 4;     // this thread's d-quad
    const int ib = tid >> 4;           // this thread's local i row (0..15)
    float4 o0 = make_float4(0.f, 0.f, 0.f, 0.f);

    for (int jc = 0; jc < NM; jc += CHUNK_J) {
        __syncthreads();   // previous consumers of s_kj done (and softmax writes visible)
        {
            const float4* src = (const float4*)(v + (size_t)(b * NM + jc) * ND);
            for (int e = tid; e < CHUNK_J * ND / 4; e += THREADS) {
                int idx = e * 4;
                int row = idx / ND, col = idx % ND;
                *(float4*)&s_kj[row * KSTRIDE + col] = src[e];
            }
        }
        __syncthreads();

        // weights fetched 4-at-a-time (one broadcast LDS.128 per 4 j)
        #pragma unroll 4
        for (int j = 0; j < CHUNK_J; j += 4) {
            float4 w = *(const float4*)&s_scores[ib * SSTRIDE + jc + j];
            float4 v0 = *(const float4*)&s_kj[(j + 0) * KSTRIDE + dx];
            float4 v1 = *(const float4*)&s_kj[(j + 1) * KSTRIDE + dx];
            float4 v2 = *(const float4*)&s_kj[(j + 2) * KSTRIDE + dx];
            float4 v3 = *(const float4*)&s_kj[(j + 3) * KSTRIDE + dx];
            o0.x += w.x * v0.x; o0.y += w.x * v0.y; o0.z += w.x * v0.z; o0.w += w.x * v0.w;
            o0.x += w.y * v1.x; o0.y += w.y * v1.y; o0.z += w.y * v1.z; o0.w += w.y * v1.w;
            o0.x += w.z * v2.x; o0.y += w.z * v2.y; o0.z += w.z * v2.z; o0.w += w.z * v2.w;
            o0.x += w.w * v3.x; o0.y += w.w * v3.y; o0.z += w.w * v3.z; o0.w += w.w * v3.w;
        }
    }

    const float inv0 = s_inv[ib];
    o0.x *= inv0; o0.y *= inv0; o0.z *= inv0; o0.w *= inv0;

    float* dst0 = out + (size_t)(b * NM + i0 + ib) * ND + dx;
    *(float4*)dst0 = o0;
}

extern "C" void kernel_launch(void* const* d_in, const int* in_sizes, int n_in,
                              void* d_out, int out_size) {
    const float* k = (const float*)d_in[0];
    const float* v = (const float*)d_in[1];
    // q (d_in[2]) is unused by the reference computation.
    (void)in_sizes; (void)n_in; (void)out_size;

    cudaFuncSetAttribute(laplace_attn_kernel,
                         cudaFuncAttributeMaxDynamicSharedMemorySize, SMEM_BYTES);

    dim3 grid(NB * (NM / TILE_I));
    laplace_attn_kernel<<<grid, THREADS, SMEM_BYTES>>>(k, v, (float*)d_out);
}

// round 5
// speedup vs baseline: 1.4677x; 1.4677x over previous
#include <cuda_runtime.h>

#define NB 8
#define NM 512
#define ND 64
#define TILE_I 16
#define CHUNK_J 256
#define THREADS 256
#define KSTRIDE 68          // padded row stride (floats) for k/v chunk tiles
#define ISTRIDE 20          // padded row stride (floats) for transposed scores

// shared layout (floats)
#define OFF_ST   0                                    // scoresT [NM][ISTRIDE] = 10240
#define OFF_VI   (NM * ISTRIDE)                       // 10240, v i-tile [16][68] = 1088
#define OFF_KJ   (OFF_VI + TILE_I * KSTRIDE)          // 11328, chunk [256][68] = 17408
#define OFF_INV  (OFF_KJ + CHUNK_J * KSTRIDE)         // 28736, [16]
#define OFF_RMAX (OFF_INV + TILE_I)                   // 28752, [2][4] float4 = 32
#define OFF_RSUM (OFF_RMAX + 32)                      // 28784, 32
#define SMEM_FLOATS (OFF_RSUM + 32)                   // 28816
#define SMEM_BYTES  (SMEM_FLOATS * 4)                 // 115264 -> 2 CTAs/SM

#define FFMA2(o, a, b) asm("fma.rn.f32x2 %0, %1, %2, %0;" : "+l"(o) : "l"(a), "l"(b))
#define PACK2(o, x, y) asm("mov.b64 %0, {%1, %2};" : "=l"(o) : "f"(x), "f"(y))
#define DUP2(o, x)     asm("mov.b64 %0, {%1, %1};" : "=l"(o) : "f"(x))
#define UNPK2(lo, hi, p) asm("mov.b64 {%0, %1}, %2;" : "=f"(lo), "=f"(hi) : "l"(p))

__global__ __launch_bounds__(THREADS, 2)
void laplace_attn_kernel(const float* __restrict__ k,
                         const float* __restrict__ v,
                         float* __restrict__ out) {
    extern __shared__ float smem[];
    float* sT     = smem + OFF_ST;    // [NM][ISTRIDE] scores, transposed
    float* s_vi   = smem + OFF_VI;    // [TILE_I][KSTRIDE]
    float* s_kj   = smem + OFF_KJ;    // [CHUNK_J][KSTRIDE]
    float* s_inv  = smem + OFF_INV;
    float* s_rmax = smem + OFF_RMAX;
    float* s_rsum = smem + OFF_RSUM;

    const int tid = threadIdx.x;
    const int b  = blockIdx.x >> 5;           // NM/TILE_I = 32 tiles/batch
    const int i0 = (blockIdx.x & 31) * TILE_I;

    // ---- stage v rows for this i-tile ----
    {
        const float4* src = (const float4*)(v + (size_t)(b * NM + i0) * ND);
        #pragma unroll
        for (int e = tid; e < TILE_I * ND / 4; e += THREADS) {
            int r = e >> 4, c = (e & 15) << 2;
            *(float4*)&s_vi[r * KSTRIDE + c] = src[e];
        }
    }

    // ---- Pass A: sT[j][i] = 0.5 * sum_d |k[j,d] - v[i,d]|, 4i x 4j per thread ----
    const int ig    = tid >> 6;   // i-group (4 rows each)
    const int jslot = tid & 63;

    for (int jc = 0; jc < NM; jc += CHUNK_J) {
        __syncthreads();
        {
            const float4* src = (const float4*)(k + (size_t)(b * NM + jc) * ND);
            #pragma unroll
            for (int e = tid; e < CHUNK_J * ND / 4; e += THREADS) {
                int r = e >> 4, c = (e & 15) << 2;
                *(float4*)&s_kj[r * KSTRIDE + c] = src[e];
            }
        }
        __syncthreads();

        float acc[4][4];
        #pragma unroll
        for (int r = 0; r < 4; ++r)
            #pragma unroll
            for (int jj = 0; jj < 4; ++jj) acc[r][jj] = 0.f;

        #pragma unroll 4
        for (int d = 0; d < ND; d += 4) {
            float4 av[4];
            #pragma unroll
            for (int r = 0; r < 4; ++r)
                av[r] = *(const float4*)&s_vi[(ig * 4 + r) * KSTRIDE + d];   // broadcast
            #pragma unroll
            for (int jj = 0; jj < 4; ++jj) {
                float4 bv = *(const float4*)&s_kj[(jslot + 64 * jj) * KSTRIDE + d];
                #pragma unroll
                for (int r = 0; r < 4; ++r) {
                    acc[r][jj] += fabsf(av[r].x - bv.x) + fabsf(av[r].y - bv.y)
                                + fabsf(av[r].z - bv.z) + fabsf(av[r].w - bv.w);
                }
            }
        }
        #pragma unroll
        for (int jj = 0; jj < 4; ++jj) {
            int j = jc + jslot + 64 * jj;
            float4 sv = make_float4(0.5f * acc[0][jj], 0.5f * acc[1][jj],
                                    0.5f * acc[2][jj], 0.5f * acc[3][jj]);
            *(float4*)&sT[j * ISTRIDE + ig * 4] = sv;    // transposed store
        }
    }
    __syncthreads();

    // ---- softmax over j for each i (reads i-quads via LDS.128) ----
    {
        const int w = tid >> 5, lane = tid & 31;
        const int iq = w >> 1;        // i-quad 0..3
        const int jh = w & 1;         // j-half 0..1 (256 j each)

        float4 mx = make_float4(-1e30f, -1e30f, -1e30f, -1e30f);
        #pragma unroll
        for (int t = 0; t < 8; ++t) {
            int j = jh * 256 + t * 32 + lane;
            float4 s = *(const float4*)&sT[j * ISTRIDE + iq * 4];
            mx.x = fmaxf(mx.x, s.x); mx.y = fmaxf(mx.y, s.y);
            mx.z = fmaxf(mx.z, s.z); mx.w = fmaxf(mx.w, s.w);
        }
        #pragma unroll
        for (int o = 16; o > 0; o >>= 1) {
            mx.x = fmaxf(mx.x, __shfl_xor_sync(0xffffffffu, mx.x, o));
            mx.y = fmaxf(mx.y, __shfl_xor_sync(0xffffffffu, mx.y, o));
            mx.z = fmaxf(mx.z, __shfl_xor_sync(0xffffffffu, mx.z, o));
            mx.w = fmaxf(mx.w, __shfl_xor_sync(0xffffffffu, mx.w, o));
        }
        if (lane == 0) *(float4*)&s_rmax[(jh * 4 + iq) * 4] = mx;
        __syncthreads();
        {
            float4 m0 = *(const float4*)&s_rmax[(0 * 4 + iq) * 4];
            float4 m1 = *(const float4*)&s_rmax[(1 * 4 + iq) * 4];
            mx.x = fmaxf(m0.x, m1.x); mx.y = fmaxf(m0.y, m1.y);
            mx.z = fmaxf(m0.z, m1.z); mx.w = fmaxf(m0.w, m1.w);
        }
        float4 sum = make_float4(0.f, 0.f, 0.f, 0.f);
        #pragma unroll
        for (int t = 0; t < 8; ++t) {
            int j = jh * 256 + t * 32 + lane;
            float4 s = *(const float4*)&sT[j * ISTRIDE + iq * 4];
            s.x = __expf(s.x - mx.x); s.y = __expf(s.y - mx.y);
            s.z = __expf(s.z - mx.z); s.w = __expf(s.w - mx.w);
            *(float4*)&sT[j * ISTRIDE + iq * 4] = s;
            sum.x += s.x; sum.y += s.y; sum.z += s.z; sum.w += s.w;
        }
        #pragma unroll
        for (int o = 16; o > 0; o >>= 1) {
            sum.x += __shfl_xor_sync(0xffffffffu, sum.x, o);
            sum.y += __shfl_xor_sync(0xffffffffu, sum.y, o);
            sum.z += __shfl_xor_sync(0xffffffffu, sum.z, o);
            sum.w += __shfl_xor_sync(0xffffffffu, sum.w, o);
        }
        if (lane == 0) *(float4*)&s_rsum[(jh * 4 + iq) * 4] = sum;
        __syncthreads();
        if (tid < TILE_I) {
            int q = tid >> 2, c = tid & 3;
            float st = s_rsum[(0 * 4 + q) * 4 + c] + s_rsum[(1 * 4 + q) * 4 + c];
            s_inv[tid] = __frcp_rn(st);
        }
    }

    // ---- Pass B: o[i][d] = sum_j e[j][i] * v[j][d]; 8i x 4d per lane, packed f32x2 ----
    const int lane  = tid & 31;
    const int w     = tid >> 5;
    const int dxq   = (lane & 15) * 4;
    const int ibase = (lane >> 4) * 8;

    unsigned long long o[4][4];     // [i-pair][d-comp], each packs (i, i+1)
    #pragma unroll
    for (int p = 0; p < 4; ++p)
        #pragma unroll
        for (int c = 0; c < 4; ++c) o[p][c] = 0ull;

    for (int jc = 0; jc < NM; jc += CHUNK_J) {
        __syncthreads();
        {
            const float4* src = (const float4*)(v + (size_t)(b * NM + jc) * ND);
            #pragma unroll
            for (int e = tid; e < CHUNK_J * ND / 4; e += THREADS) {
                int r = e >> 4, c = (e & 15) << 2;
                *(float4*)&s_kj[r * KSTRIDE + c] = src[e];
            }
        }
        __syncthreads();

        #pragma unroll 4
        for (int jt = 0; jt < 32; ++jt) {           // this warp's j-range
            int j = jc + w * 32 + jt;
            float4 w0 = *(const float4*)&sT[j * ISTRIDE + ibase];       // broadcast
            float4 w1 = *(const float4*)&sT[j * ISTRIDE + ibase + 4];   // broadcast
            float4 vv = *(const float4*)&s_kj[(j - jc) * KSTRIDE + dxq];

            unsigned long long wp0, wp1, wp2, wp3, vd0, vd1, vd2, vd3;
            PACK2(wp0, w0.x, w0.y); PACK2(wp1, w0.z, w0.w);
            PACK2(wp2, w1.x, w1.y); PACK2(wp3, w1.z, w1.w);
            DUP2(vd0, vv.x); DUP2(vd1, vv.y); DUP2(vd2, vv.z); DUP2(vd3, vv.w);

            FFMA2(o[0][0], wp0, vd0); FFMA2(o[0][1], wp0, vd1);
            FFMA2(o[0][2], wp0, vd2); FFMA2(o[0][3], wp0, vd3);
            FFMA2(o[1][0], wp1, vd0); FFMA2(o[1][1], wp1, vd1);
            FFMA2(o[1][2], wp1, vd2); FFMA2(o[1][3], wp1, vd3);
            FFMA2(o[2][0], wp2, vd0); FFMA2(o[2][1], wp2, vd1);
            FFMA2(o[2][2], wp2, vd2); FFMA2(o[2][3], wp2, vd3);
            FFMA2(o[3][0], wp3, vd0); FFMA2(o[3][1], wp3, vd1);
            FFMA2(o[3][2], wp3, vd2); FFMA2(o[3][3], wp3, vd3);
        }
    }

    // ---- reduce the 8 per-warp partials through smem (overlay on s_kj) ----
    __syncthreads();
    float* red = s_kj;              // [8][TILE_I][KSTRIDE]
    #pragma unroll
    for (int p = 0; p < 4; ++p) {
        float lo0, lo1, lo2, lo3, hi0, hi1, hi2, hi3;
        UNPK2(lo0, hi0, o[p][0]); UNPK2(lo1, hi1, o[p][1]);
        UNPK2(lo2, hi2, o[p][2]); UNPK2(lo3, hi3, o[p][3]);
        *(float4*)&red[(w * TILE_I + ibase + 2 * p    ) * KSTRIDE + dxq] =
            make_float4(lo0, lo1, lo2, lo3);
        *(float4*)&red[(w * TILE_I + ibase + 2 * p + 1) * KSTRIDE + dxq] =
            make_float4(hi0, hi1, hi2, hi3);
    }
    __syncthreads();

    {
        const int fi  = tid >> 4;
        const int fdx = (tid & 15) * 4;
        float4 a = make_float4(0.f, 0.f, 0.f, 0.f);
        #pragma unroll
        for (int ww = 0; ww < 8; ++ww) {
            float4 t = *(const float4*)&red[(ww * TILE_I + fi) * KSTRIDE + fdx];
            a.x += t.x; a.y += t.y; a.z += t.z; a.w += t.w;
        }
        const float inv = s_inv[fi];
        a.x *= inv; a.y *= inv; a.z *= inv; a.w *= inv;
        *(float4*)(out + (size_t)(b * NM + i0 + fi) * ND + fdx) = a;
    }
}

extern "C" void kernel_launch(void* const* d_in, const int* in_sizes, int n_in,
                              void* d_out, int out_size) {
    const float* k = (const float*)d_in[0];
    const float* v = (const float*)d_in[1];
    // q (d_in[2]) is unused by the reference computation.
    (void)in_sizes; (void)n_in; (void)out_size;

    cudaFuncSetAttribute(laplace_attn_kernel,
                         cudaFuncAttributeMaxDynamicSharedMemorySize, SMEM_BYTES);

    dim3 grid(NB * (NM / TILE_I));
    laplace_attn_kernel<<<grid, THREADS, SMEM_BYTES>>>(k, v, (float*)d_out);
}